// round 11
// baseline (speedup 1.0000x reference)
#include <cuda_runtime.h>

// ---------------- problem constants ----------------
#define NNODES 139425          // 65*65*33
#define NCELLS 131072          // 64*64*32
#define NACT   81920
#define EPSD   1.0e-7f
#define ATOL2  2.0e-12         // (1e-6)^2 * ||b||^2, ||b||^2 = 2
#define NCX 137280
#define NCY 137280
#define NCZ 135200
#define CG_ITERS 100
#define NBLK 137               // ceil(139425/1024)
#define NTHR 1024
#define DSMEM (3*4*1024*16)    // p, r, q tiles (float4): 196608 B

// ---------------- device scratch ----------------
__device__ float4 g_r0[NNODES*4];      // r exchange, double-buffered
__device__ float4 g_r1[NNODES*4];
__device__ float4 g_q0[NNODES*4];      // q exchange, double-buffered
__device__ float4 g_q1[NNODES*4];
__device__ float  g_sigma[NCELLS];
__device__ float  g_cx[NCX];
__device__ float  g_cy[NCY];
__device__ float  g_cz[NCZ];
__device__ double g_dot[48];           // pq[0..15], rq[16..31], qq[32..47]
__device__ double g_gamd[16];
__device__ float  g_xsel[32*16];
__device__ float  g_ab[32];            // alpha[0..15], beta[16..31]
__device__ int    g_froz[16];
__device__ unsigned g_cnt;
__device__ volatile unsigned g_rel2;

// ---------------- setup kernels ----------------
__global__ void k_init_sigma() {
    int t = blockIdx.x*blockDim.x + threadIdx.x;
    if (t < NCELLS) g_sigma[t] = 1.0e-8f;            // 1/AIR_RES
}

__global__ void k_scatter(const int* __restrict__ act, const float* __restrict__ model) {
    int t = blockIdx.x*blockDim.x + threadIdx.x;
    if (t < NACT) g_sigma[act[t]] = 1.0f / model[t];
}

__global__ void k_coeffs() {
    int t = blockIdx.x*blockDim.x + threadIdx.x;
    if (t < NCX) {
        int k = t % 33; int r = t / 33; int j = r % 65; int i = r / 65;
        float s = 0.f;
        for (int jj = j-1; jj <= j; ++jj)
            for (int kk = k-1; kk <= k; ++kk)
                if (jj >= 0 && jj < 64 && kk >= 0 && kk < 32)
                    s += g_sigma[(i*64 + jj)*32 + kk];
        g_cx[t] = 6.25f * s;                          // 0.25 * 25.0
    } else if (t < NCX + NCY) {
        int e = t - NCX;
        int k = e % 33; int r = e / 33; int j = r % 64; int i = r / 64;
        float s = 0.f;
        for (int ii = i-1; ii <= i; ++ii)
            for (int kk = k-1; kk <= k; ++kk)
                if (ii >= 0 && ii < 64 && kk >= 0 && kk < 32)
                    s += g_sigma[(ii*64 + j)*32 + kk];
        g_cy[e] = 6.25f * s;
    } else if (t < NCX + NCY + NCZ) {
        int e = t - NCX - NCY;
        int k = e % 32; int r = e / 32; int j = r % 65; int i = r / 65;
        float s = 0.f;
        for (int ii = i-1; ii <= i; ++ii)
            for (int jj = j-1; jj <= j; ++jj)
                if (ii >= 0 && ii < 64 && jj >= 0 && jj < 64)
                    s += g_sigma[(ii*64 + jj)*32 + k];
        g_cz[e] = 6.25f * s;
    }
}

// per-launch state reset (runs on every graph replay)
__global__ void k_zero() {
    int t = blockIdx.x*blockDim.x + threadIdx.x;
    if (t < NNODES*4) {
        float4 z = make_float4(0.f,0.f,0.f,0.f);
        g_r0[t] = z; g_r1[t] = z; g_q0[t] = z; g_q1[t] = z;
    }
    if (t < 32*16) g_xsel[t] = 0.f;
    if (t < 48) g_dot[t] = 0.0;
    if (t < 32) g_ab[t] = 0.f;
    if (t < 16) { g_gamd[t] = 2.0; g_froz[t] = 0; }
}

// set r = b into g_r1 (pass 0's read buffer)
__global__ void k_setb(const int* __restrict__ sa, const int* __restrict__ sb) {
    int s = threadIdx.x;
    if (s < 16) {
        float* rf = (float*)g_r1;
        rf[sa[s]*16 + s]  = 1.0f;
        rf[sb[s]*16 + s] -= 1.0f;
    }
}

// warp-shuffle reduce 4 floats (one quad) -> arr[wid*16 + 4u + c]
#define QUADRED(arr, v0, v1, v2, v3, u)                                        \
    {                                                                          \
        float a0=(v0), a1=(v1), a2=(v2), a3=(v3);                              \
        a0 += __shfl_down_sync(0xffffffffu, a0, 16);                           \
        a1 += __shfl_down_sync(0xffffffffu, a1, 16);                           \
        a2 += __shfl_down_sync(0xffffffffu, a2, 16);                           \
        a3 += __shfl_down_sync(0xffffffffu, a3, 16);                           \
        a0 += __shfl_down_sync(0xffffffffu, a0, 8);                            \
        a1 += __shfl_down_sync(0xffffffffu, a1, 8);                            \
        a2 += __shfl_down_sync(0xffffffffu, a2, 8);                            \
        a3 += __shfl_down_sync(0xffffffffu, a3, 8);                            \
        a0 += __shfl_down_sync(0xffffffffu, a0, 4);                            \
        a1 += __shfl_down_sync(0xffffffffu, a1, 4);                            \
        a2 += __shfl_down_sync(0xffffffffu, a2, 4);                            \
        a3 += __shfl_down_sync(0xffffffffu, a3, 4);                            \
        a0 += __shfl_down_sync(0xffffffffu, a0, 2);                            \
        a1 += __shfl_down_sync(0xffffffffu, a1, 2);                            \
        a2 += __shfl_down_sync(0xffffffffu, a2, 2);                            \
        a3 += __shfl_down_sync(0xffffffffu, a3, 2);                            \
        a0 += __shfl_down_sync(0xffffffffu, a0, 1);                            \
        a1 += __shfl_down_sync(0xffffffffu, a1, 1);                            \
        a2 += __shfl_down_sync(0xffffffffu, a2, 1);                            \
        a3 += __shfl_down_sync(0xffffffffu, a3, 1);                            \
        if (lane == 0) {                                                       \
            (arr)[wid*16 + 4*(u) + 0] = a0;                                    \
            (arr)[wid*16 + 4*(u) + 1] = a1;                                    \
            (arr)[wid*16 + 4*(u) + 2] = a2;                                    \
            (arr)[wid*16 + 4*(u) + 3] = a3;                                    \
        }                                                                      \
    }

// reconstruct + accumulate one global neighbor quad: pn = r[n] - alpha*q[n]
#define ACCG(off)                                                              \
    {                                                                          \
        float4 nr = rd_r[base4 + (off) + u];                                   \
        float4 nq = rd_q[base4 + (off) + u];                                   \
        float e0 = fmaf(-al0, nq.x, nr.x);                                     \
        float e1 = fmaf(-al1, nq.y, nr.y);                                     \
        float e2 = fmaf(-al2, nq.z, nr.z);                                     \
        float e3 = fmaf(-al3, nq.w, nr.w);                                     \
        q0 = fmaf(c_, p0 - e0, q0);                                            \
        q1 = fmaf(c_, p1 - e1, q1);                                            \
        q2 = fmaf(c_, p2 - e2, q2);                                            \
        q3 = fmaf(c_, p3 - e3, q3);                                            \
    }

// accumulate one smem neighbor quad (already r_new)
#define ACCS(pn)                                                               \
    {                                                                          \
        q0 = fmaf(c_, p0 - (pn).x, q0);                                        \
        q1 = fmaf(c_, p1 - (pn).y, q1);                                        \
        q2 = fmaf(c_, p2 - (pn).z, q2);                                        \
        q3 = fmaf(c_, p3 - (pn).w, q3);                                        \
    }

// ---------------- persistent CG kernel (1 barrier / iteration) ----------------
__global__ void __launch_bounds__(NTHR, 1)
k_persist(const int* __restrict__ rxm, const int* __restrict__ rxn)
{
    extern __shared__ float4 s_dyn[];
    float4* s_p = s_dyn;               // [4][1024]
    float4* s_r = s_dyn + 4096;        // [4][1024]
    float4* s_q = s_dyn + 8192;        // [4][1024]

    const int tid = threadIdx.x;
    const int lane = tid & 31;
    const int wid  = tid >> 5;
    const int node = blockIdx.x*NTHR + tid;
    const bool valid = node < NNODES;

    int base4 = 0;
    float cxp=0.f, cxm=0.f, cyp=0.f, cym=0.f, czp=0.f, czm=0.f;
    if (valid) {
        int k = node % 33;
        int ij = node / 33;
        int j = ij % 65;
        int i = ij / 65;
        base4 = node * 4;
        if (i < 64) cxp = g_cx[(i*65 + j)*33 + k];
        if (i > 0)  cxm = g_cx[((i-1)*65 + j)*33 + k];
        if (j < 64) cyp = g_cy[(i*64 + j)*33 + k];
        if (j > 0)  cym = g_cy[(i*64 + (j-1))*33 + k];
        if (k < 32) czp = g_cz[(i*65 + j)*32 + k];
        if (k > 0)  czm = g_cz[(i*65 + j)*32 + (k-1)];
    }

    // receiver-slot ownership (32 distinct nodes)
    int slot = -1;
    if (valid) {
        for (int r2 = 0; r2 < 16; r2++) {
            if (node == rxm[r2]) slot = r2;
            if (node == rxn[r2]) slot = 16 + r2;
        }
    }

    // init tiles: r = b (g_r1), p = q = 0
    {
        float4 z = make_float4(0.f,0.f,0.f,0.f);
        #pragma unroll
        for (int u = 0; u < 4; u++) {
            s_p[u*1024+tid] = z;
            s_q[u*1024+tid] = z;
            s_r[u*1024+tid] = valid ? g_r1[base4+u] : z;
        }
    }

    __shared__ float  s_redP[32*16];   // p.q partials
    __shared__ float  s_redR[32*16];   // r.q partials
    __shared__ float  s_redQ[32*16];   // q.q partials
    __shared__ float  s_alpha[16], s_beta[16];
    __shared__ int    s_last;
    if (tid < 16) { s_alpha[tid] = 0.f; s_beta[tid] = 0.f; }
    __syncthreads();

    unsigned gen = g_rel2;

    #pragma unroll 1
    for (int it = 0; it < CG_ITERS; ++it) {
        const float4* __restrict__ rd_r = (it & 1) ? g_r0 : g_r1;
        const float4* __restrict__ rd_q = (it & 1) ? g_q0 : g_q1;
        float4* __restrict__       wr_r = (it & 1) ? g_r1 : g_r0;
        float4* __restrict__       wr_q = (it & 1) ? g_q1 : g_q0;

        // ---- step 1: x += alpha_prev * p_prev (slot owners);
        //      r_new = r - alpha_prev * q_prev; publish r_new ----
        if (slot >= 0) {
            #pragma unroll
            for (int u = 0; u < 4; u++) {
                float4 pv = s_p[u*1024+tid];
                g_xsel[slot*16 + 4*u+0] += s_alpha[4*u+0] * pv.x;
                g_xsel[slot*16 + 4*u+1] += s_alpha[4*u+1] * pv.y;
                g_xsel[slot*16 + 4*u+2] += s_alpha[4*u+2] * pv.z;
                g_xsel[slot*16 + 4*u+3] += s_alpha[4*u+3] * pv.w;
            }
        }
        #pragma unroll
        for (int u = 0; u < 4; u++) {
            float4 rv = s_r[u*1024+tid];
            float4 qv = s_q[u*1024+tid];
            rv.x = fmaf(-s_alpha[4*u+0], qv.x, rv.x);
            rv.y = fmaf(-s_alpha[4*u+1], qv.y, rv.y);
            rv.z = fmaf(-s_alpha[4*u+2], qv.z, rv.z);
            rv.w = fmaf(-s_alpha[4*u+3], qv.w, rv.w);
            s_r[u*1024+tid] = rv;
            if (valid) wr_r[base4+u] = rv;
        }
        __syncthreads();

        // ---- step 2: stencil on r_new (in-block smem; cross-block
        //      reconstruct r_new[n] = rd_r[n] - alpha*rd_q[n]);
        //      q = A r_new + beta*q_old; p = r_new + beta*p_old;
        //      dots pq, rq, qq; publish q ----
        #pragma unroll
        for (int u = 0; u < 4; u++) {
            float al0 = s_alpha[4*u+0], al1 = s_alpha[4*u+1];
            float al2 = s_alpha[4*u+2], al3 = s_alpha[4*u+3];
            float ba0 = s_beta[4*u+0], ba1 = s_beta[4*u+1];
            float ba2 = s_beta[4*u+2], ba3 = s_beta[4*u+3];
            float4 rv = s_r[u*1024+tid];
            float p0 = rv.x, p1 = rv.y, p2 = rv.z, p3 = rv.w;   // r_new
            float q0 = EPSD*p0, q1 = EPSD*p1, q2 = EPSD*p2, q3 = EPSD*p3;
            if (cxp != 0.f) { float c_ = cxp; ACCG(8580); }
            if (cxm != 0.f) { float c_ = cxm; ACCG(-8580); }
            if (cyp != 0.f) {
                float c_ = cyp;
                if (tid + 33 < NTHR) { float4 pn = s_r[u*1024+tid+33]; ACCS(pn); }
                else                 { ACCG(132); }
            }
            if (cym != 0.f) {
                float c_ = cym;
                if (tid >= 33) { float4 pn = s_r[u*1024+tid-33]; ACCS(pn); }
                else           { ACCG(-132); }
            }
            if (czp != 0.f) {
                float c_ = czp;
                if (tid + 1 < NTHR) { float4 pn = s_r[u*1024+tid+1]; ACCS(pn); }
                else                { ACCG(4); }
            }
            if (czm != 0.f) {
                float c_ = czm;
                if (tid >= 1) { float4 pn = s_r[u*1024+tid-1]; ACCS(pn); }
                else          { ACCG(-4); }
            }
            // q = A r + beta*q_old ; p = r + beta*p_old
            float4 qo = s_q[u*1024+tid];
            float4 po = s_p[u*1024+tid];
            q0 = fmaf(ba0, qo.x, q0); q1 = fmaf(ba1, qo.y, q1);
            q2 = fmaf(ba2, qo.z, q2); q3 = fmaf(ba3, qo.w, q3);
            float n0 = fmaf(ba0, po.x, p0), n1 = fmaf(ba1, po.y, p1);
            float n2 = fmaf(ba2, po.z, p2), n3 = fmaf(ba3, po.w, p3);
            float4 qn = make_float4(q0, q1, q2, q3);
            s_q[u*1024+tid] = qn;
            s_p[u*1024+tid] = make_float4(n0, n1, n2, n3);
            if (valid) wr_q[base4+u] = qn;
            QUADRED(s_redP, n0*q0, n1*q1, n2*q2, n3*q3, u);
            QUADRED(s_redR, p0*q0, p1*q1, p2*q2, p3*q3, u);
            QUADRED(s_redQ, q0*q0, q1*q1, q2*q2, q3*q3, u);
        }
        __syncthreads();
        if (tid < 48) {
            const float* src = (tid < 16) ? s_redP : (tid < 32) ? s_redR : s_redQ;
            int c = tid & 15;
            float acc = 0.f;
            #pragma unroll
            for (int w = 0; w < 32; w++) acc += src[w*16 + c];
            atomicAdd(&g_dot[tid], (double)acc);
        }

        // ---- barrier: last block computes alpha_i, gamma_{i+1}, beta_{i+1} ----
        gen++;
        __syncthreads();
        if (tid == 0) {
            __threadfence();
            unsigned old = atomicAdd(&g_cnt, 1u);
            s_last = (old == gen*NBLK - 1u) ? 1 : 0;
        }
        __syncthreads();
        if (s_last) {
            if (tid < 16) {
                double pq = g_dot[tid];
                double rq = g_dot[16 + tid];
                double qq = g_dot[32 + tid];
                double gam = g_gamd[tid];
                double alpha = 0.0, beta = 0.0;
                if (!g_froz[tid]) {
                    alpha = gam / pq;
                    double gn = gam - 2.0*alpha*rq + alpha*alpha*qq;
                    beta = gn / gam;
                    g_gamd[tid] = gn;
                    if (gn <= ATOL2) g_froz[tid] = 1;
                }
                g_ab[tid]      = (float)alpha;
                g_ab[16 + tid] = (float)beta;
                g_dot[tid] = 0.0;
                g_dot[16 + tid] = 0.0;
                g_dot[32 + tid] = 0.0;
                __threadfence();
            }
            __syncthreads();
            if (tid == 0) { g_rel2 = gen; }
            __syncthreads();
        } else {
            if (tid == 0) {
                while (g_rel2 < gen) { }
                __threadfence();
            }
            __syncthreads();
        }
        if (tid < 16) { s_alpha[tid] = g_ab[tid]; s_beta[tid] = g_ab[16 + tid]; }
        __syncthreads();
    }

    // epilogue: final x += alpha_99 * p_99
    if (slot >= 0) {
        #pragma unroll
        for (int u = 0; u < 4; u++) {
            float4 pv = s_p[u*1024+tid];
            g_xsel[slot*16 + 4*u+0] += s_alpha[4*u+0] * pv.x;
            g_xsel[slot*16 + 4*u+1] += s_alpha[4*u+1] * pv.y;
            g_xsel[slot*16 + 4*u+2] += s_alpha[4*u+2] * pv.z;
            g_xsel[slot*16 + 4*u+3] += s_alpha[4*u+3] * pv.w;
        }
    }
}

// ---------------- loss ----------------
__global__ void k_loss(const float* __restrict__ infm, const float* __restrict__ start,
                       const float* __restrict__ ref, float* __restrict__ out) {
    __shared__ double sd[256];
    __shared__ double sm[256];
    int t = threadIdx.x;
    int s = t >> 4;                   // source index
    int r = t & 15;                   // receiver index
    float d = g_xsel[r*16 + s] - g_xsel[(16+r)*16 + s];
    float diff = d - ref[t];
    sd[t] = (double)diff * (double)diff;
    double lm = 0.0;
    for (int idx = t; idx < NACT; idx += 256) {
        float dd = infm[idx] - start[idx];
        lm += (double)dd * (double)dd;
    }
    sm[t] = lm;
    __syncthreads();
    for (int off = 128; off >= 1; off >>= 1) {
        if (t < off) { sd[t] += sd[t+off]; sm[t] += sm[t+off]; }
        __syncthreads();
    }
    if (t == 0) {
        float loss_data  = (float)(sd[0] / 256.0);
        float loss_model = (float)(sm[0] / (double)NACT);
        out[0] = loss_data;           // alpha = 0.0 -> total == loss_data
        out[1] = loss_data;
        out[2] = loss_model;
    }
}

// ---------------- launch ----------------
extern "C" void kernel_launch(void* const* d_in, const int* in_sizes, int n_in,
                              void* d_out, int out_size) {
    const float* infm  = (const float*)d_in[0];
    const float* start = (const float*)d_in[1];
    const float* dref  = (const float*)d_in[2];
    const int*   act   = (const int*)  d_in[3];
    const int*   sa    = (const int*)  d_in[4];
    const int*   sb    = (const int*)  d_in[5];
    const int*   rxm   = (const int*)  d_in[6];
    const int*   rxn   = (const int*)  d_in[7];
    float* out = (float*)d_out;

    static int attr_done = 0;
    if (!attr_done) {
        cudaFuncSetAttribute(k_persist, cudaFuncAttributeMaxDynamicSharedMemorySize, DSMEM);
        attr_done = 1;
    }

    k_init_sigma<<<(NCELLS+255)/256, 256>>>();
    k_scatter<<<(NACT+255)/256, 256>>>(act, infm);
    k_coeffs<<<(NCX+NCY+NCZ+255)/256, 256>>>();
    k_zero<<<(NNODES*4+255)/256, 256>>>();
    k_setb<<<1, 32>>>(sa, sb);
    k_persist<<<NBLK, NTHR, DSMEM>>>(rxm, rxn);
    k_loss<<<1, 256>>>(infm, start, dref, out);
}

// round 15
// speedup vs baseline: 1.4008x; 1.4008x over previous
#include <cuda_runtime.h>
#include <cstdint>

// ---------------- problem constants ----------------
#define NNODES 139425          // 65*65*33
#define NCELLS 131072          // 64*64*32
#define NACT   81920
#define EPSD   1.0e-7f
#define ATOL2  2.0e-12         // (1e-6)^2 * ||b||^2, ||b||^2 = 2
#define NCX 137280
#define NCY 137280
#define NCZ 135200
#define CG_ITERS 100
#define NBLK 137               // ceil(139425/1024)
#define NTHR 1024
#define DSMEM (3*4*1024*16)    // p, r, q tiles (float4): 196608 B

// ---------------- device scratch ----------------
__device__ float4 g_r[NNODES*4];       // exchanged vector: residual r
__device__ float  g_sigma[NCELLS];
__device__ float  g_cx[NCX];
__device__ float  g_cy[NCY];
__device__ float  g_cz[NCZ];
__device__ double g_dotA[16];          // p.q accumulators
__device__ double g_dotB[16];          // r.r accumulators
__device__ float  g_xsel[32*16];
__device__ float  g_ab[32];            // alpha[0..15], beta[16..31]
__device__ float  g_gam[16];
__device__ int    g_froz[16];
__device__ unsigned g_cnt;
__device__ volatile unsigned g_rel2;

// ---------------- setup kernels ----------------
__global__ void k_init_sigma() {
    int t = blockIdx.x*blockDim.x + threadIdx.x;
    if (t < NCELLS) g_sigma[t] = 1.0e-8f;            // 1/AIR_RES
}

__global__ void k_scatter(const int* __restrict__ act, const float* __restrict__ model) {
    int t = blockIdx.x*blockDim.x + threadIdx.x;
    if (t < NACT) g_sigma[act[t]] = 1.0f / model[t];
}

__global__ void k_coeffs() {
    int t = blockIdx.x*blockDim.x + threadIdx.x;
    if (t < NCX) {
        int k = t % 33; int r = t / 33; int j = r % 65; int i = r / 65;
        float s = 0.f;
        for (int jj = j-1; jj <= j; ++jj)
            for (int kk = k-1; kk <= k; ++kk)
                if (jj >= 0 && jj < 64 && kk >= 0 && kk < 32)
                    s += g_sigma[(i*64 + jj)*32 + kk];
        g_cx[t] = 6.25f * s;                          // 0.25 * 25.0
    } else if (t < NCX + NCY) {
        int e = t - NCX;
        int k = e % 33; int r = e / 33; int j = r % 64; int i = r / 64;
        float s = 0.f;
        for (int ii = i-1; ii <= i; ++ii)
            for (int kk = k-1; kk <= k; ++kk)
                if (ii >= 0 && ii < 64 && kk >= 0 && kk < 32)
                    s += g_sigma[(ii*64 + j)*32 + kk];
        g_cy[e] = 6.25f * s;
    } else if (t < NCX + NCY + NCZ) {
        int e = t - NCX - NCY;
        int k = e % 32; int r = e / 32; int j = r % 65; int i = r / 65;
        float s = 0.f;
        for (int ii = i-1; ii <= i; ++ii)
            for (int jj = j-1; jj <= j; ++jj)
                if (ii >= 0 && ii < 64 && jj >= 0 && jj < 64)
                    s += g_sigma[(ii*64 + jj)*32 + k];
        g_cz[e] = 6.25f * s;
    }
}

// per-launch state reset (runs on every graph replay)
__global__ void k_zero() {
    int t = blockIdx.x*blockDim.x + threadIdx.x;
    if (t < NNODES*4) g_r[t] = make_float4(0.f,0.f,0.f,0.f);
    if (t < 32*16) g_xsel[t] = 0.f;
    if (t < 32) g_ab[t] = 0.f;
    if (t < 16) {
        g_gam[t] = 2.f; g_froz[t] = 0;
        g_dotA[t] = 0.0; g_dotB[t] = 0.0;
    }
    // g_cnt / g_rel2 are monotone — never reset
}

// set r = b (separate kernel: ordering vs zero-fill via launch boundary)
__global__ void k_setb(const int* __restrict__ sa, const int* __restrict__ sb) {
    int s = threadIdx.x;
    if (s < 16) {
        float* rf = (float*)g_r;
        rf[sa[s]*16 + s]  = 1.0f;
        rf[sb[s]*16 + s] -= 1.0f;
    }
}

// folded warp reduce of 4 values across 32 lanes: 9 SHFL instead of 20.
// After fold stages, lane 8k holds total for c=(lane>>3)&3.
#define QUADRED(v0, v1, v2, v3, u)                                             \
    {                                                                          \
        float t0 = __shfl_xor_sync(0xffffffffu, (v0), 16);                     \
        float t1 = __shfl_xor_sync(0xffffffffu, (v1), 16);                     \
        float t2 = __shfl_xor_sync(0xffffffffu, (v2), 16);                     \
        float t3 = __shfl_xor_sync(0xffffffffu, (v3), 16);                     \
        float b0 = (lane & 16) ? ((v2) + t2) : ((v0) + t0);                    \
        float b1 = (lane & 16) ? ((v3) + t3) : ((v1) + t1);                    \
        t0 = __shfl_xor_sync(0xffffffffu, b0, 8);                              \
        t1 = __shfl_xor_sync(0xffffffffu, b1, 8);                              \
        float cr = (lane & 8) ? (b1 + t1) : (b0 + t0);                         \
        cr += __shfl_xor_sync(0xffffffffu, cr, 4);                             \
        cr += __shfl_xor_sync(0xffffffffu, cr, 2);                             \
        cr += __shfl_xor_sync(0xffffffffu, cr, 1);                             \
        if ((lane & 7) == 0)                                                   \
            s_red[wid*16 + 4*(u) + ((lane >> 3) & 3)] = cr;                    \
    }

// cross-warp finish + atomic publish into 16 doubles
#define PUBRED(gdst)                                                           \
    {                                                                          \
        __syncthreads();                                                       \
        if (tid < 16) {                                                        \
            float acc = 0.f;                                                   \
            _Pragma("unroll")                                                  \
            for (int w = 0; w < 32; w++) acc += s_red[w*16 + tid];             \
            atomicAdd(&(gdst)[tid], (double)acc);                              \
        }                                                                      \
    }

// barrier arrive: counter-based; sets s_last in the last-arriving block
#define BAR_ARRIVE()                                                           \
    gen++;                                                                     \
    __syncthreads();                                                           \
    if (tid == 0) {                                                            \
        __threadfence();                                                       \
        unsigned old = atomicAdd(&g_cnt, 1u);                                  \
        s_last = (old == gen*(unsigned)NBLK - 1u) ? 1 : 0;                     \
    }                                                                          \
    __syncthreads();

#define BAR_WAIT()                                                             \
    if (tid == 0) {                                                            \
        while (g_rel2 < gen) { }                                               \
        __threadfence();                                                       \
    }                                                                          \
    __syncthreads();

// accumulate one neighbor quad into q0..q3 (stencil on r)
#define ACC(pn)                                                                \
    {                                                                          \
        q0 = fmaf(c_, p0 - (pn).x, q0);                                        \
        q1 = fmaf(c_, p1 - (pn).y, q1);                                        \
        q2 = fmaf(c_, p2 - (pn).z, q2);                                        \
        q3 = fmaf(c_, p3 - (pn).w, q3);                                        \
    }

// ---------------- persistent CG kernel (2 barriers / iteration) ----------------
__global__ void __launch_bounds__(NTHR, 1)
k_persist(const int* __restrict__ rxm, const int* __restrict__ rxn)
{
    extern __shared__ float4 s_dyn[];
    float4* s_p = s_dyn;               // [4][1024] p (local only)
    float4* s_r = s_dyn + 4096;        // [4][1024] r (exchanged via g_r)
    float4* s_q = s_dyn + 8192;        // [4][1024] q (local only)

    const int tid = threadIdx.x;
    const int lane = tid & 31;
    const int wid  = tid >> 5;
    const int node = blockIdx.x*NTHR + tid;
    const bool valid = node < NNODES;

    int base4 = 0;
    float cxp=0.f, cxm=0.f, cyp=0.f, cym=0.f, czp=0.f, czm=0.f;
    if (valid) {
        int k = node % 33;
        int ij = node / 33;
        int j = ij % 65;
        int i = ij / 65;
        base4 = node * 4;
        if (i < 64) cxp = g_cx[(i*65 + j)*33 + k];
        if (i > 0)  cxm = g_cx[((i-1)*65 + j)*33 + k];
        if (j < 64) cyp = g_cy[(i*64 + j)*33 + k];
        if (j > 0)  cym = g_cy[(i*64 + (j-1))*33 + k];
        if (k < 32) czp = g_cz[(i*65 + j)*32 + k];
        if (k > 0)  czm = g_cz[(i*65 + j)*32 + (k-1)];
    }

    // receiver-slot ownership (32 distinct nodes)
    int slot = -1;
    if (valid) {
        for (int r2 = 0; r2 < 16; r2++) {
            if (node == rxm[r2]) slot = r2;
            if (node == rxn[r2]) slot = 16 + r2;
        }
    }

    // init tiles: p = 0, q = 0, r from g_r (holds b, set by k_setb)
    {
        float4 z = make_float4(0.f,0.f,0.f,0.f);
        #pragma unroll
        for (int u = 0; u < 4; u++) {
            s_p[u*1024+tid] = z;
            s_q[u*1024+tid] = z;
            s_r[u*1024+tid] = valid ? g_r[base4+u] : z;
        }
    }

    __shared__ float  s_red[32*16];
    __shared__ float  s_alpha[16], s_beta[16];
    __shared__ int    s_last;
    if (tid < 16) s_beta[tid] = 0.f;
    __syncthreads();

    unsigned gen = g_rel2;       // stable generation base from previous launch

    #pragma unroll 1
    for (int it = 0; it < CG_ITERS; ++it) {
        // ---- phase A: Ar stencil; q = Ar + beta*q_old; p = r + beta*p_old;
        //      partial p.q ----
        #pragma unroll
        for (int u = 0; u < 4; u++) {
            float4 rv = s_r[u*1024+tid];
            float p0 = rv.x, p1 = rv.y, p2 = rv.z, p3 = rv.w;   // r components
            float q0 = EPSD*p0, q1 = EPSD*p1, q2 = EPSD*p2, q3 = EPSD*p3;
            if (cxp != 0.f) { float c_ = cxp; float4 pn = g_r[base4 + 8580 + u]; ACC(pn); }
            if (cxm != 0.f) { float c_ = cxm; float4 pn = g_r[base4 - 8580 + u]; ACC(pn); }
            if (cyp != 0.f) {
                float c_ = cyp;
                float4 pn = (tid + 33 < NTHR) ? s_r[u*1024+tid+33] : g_r[base4 + 132 + u];
                ACC(pn);
            }
            if (cym != 0.f) {
                float c_ = cym;
                float4 pn = (tid >= 33) ? s_r[u*1024+tid-33] : g_r[base4 - 132 + u];
                ACC(pn);
            }
            if (czp != 0.f) {
                float c_ = czp;
                float4 pn = (tid + 1 < NTHR) ? s_r[u*1024+tid+1] : g_r[base4 + 4 + u];
                ACC(pn);
            }
            if (czm != 0.f) {
                float c_ = czm;
                float4 pn = (tid >= 1) ? s_r[u*1024+tid-1] : g_r[base4 - 4 + u];
                ACC(pn);
            }
            // q = Ar + beta*q_old ; p = r + beta*p_old
            float4 qo = s_q[u*1024+tid];
            float4 po = s_p[u*1024+tid];
            q0 = fmaf(s_beta[4*u+0], qo.x, q0);
            q1 = fmaf(s_beta[4*u+1], qo.y, q1);
            q2 = fmaf(s_beta[4*u+2], qo.z, q2);
            q3 = fmaf(s_beta[4*u+3], qo.w, q3);
            float n0 = fmaf(s_beta[4*u+0], po.x, p0);
            float n1 = fmaf(s_beta[4*u+1], po.y, p1);
            float n2 = fmaf(s_beta[4*u+2], po.z, p2);
            float n3 = fmaf(s_beta[4*u+3], po.w, p3);
            s_q[u*1024+tid] = make_float4(q0, q1, q2, q3);
            s_p[u*1024+tid] = make_float4(n0, n1, n2, n3);
            QUADRED(n0*q0, n1*q1, n2*q2, n3*q3, u);
        }
        PUBRED(g_dotA);

        // ---- barrier B: last block computes alpha from g_dotA ----
        BAR_ARRIVE();
        if (s_last) {
            if (tid < 16) {
                double pq = g_dotA[tid];
                float a = g_froz[tid] ? 0.f : g_gam[tid] / (float)pq;
                g_ab[tid] = a;
                g_dotA[tid] = 0.0;
                __threadfence();
            }
            __syncthreads();
            if (tid == 0) { g_rel2 = gen; }
            __syncthreads();
        } else {
            BAR_WAIT();
        }
        if (tid < 16) s_alpha[tid] = g_ab[tid];
        __syncthreads();

        // ---- phase B: r -= alpha q (smem + publish); x_rx += alpha p; r.r ----
        #pragma unroll
        for (int u = 0; u < 4; u++) {
            float4 rv = s_r[u*1024+tid];
            float4 qv = s_q[u*1024+tid];
            rv.x = fmaf(-s_alpha[4*u+0], qv.x, rv.x);
            rv.y = fmaf(-s_alpha[4*u+1], qv.y, rv.y);
            rv.z = fmaf(-s_alpha[4*u+2], qv.z, rv.z);
            rv.w = fmaf(-s_alpha[4*u+3], qv.w, rv.w);
            s_r[u*1024+tid] = rv;
            if (valid) g_r[base4+u] = rv;
            QUADRED(rv.x*rv.x, rv.y*rv.y, rv.z*rv.z, rv.w*rv.w, u);
        }
        if (slot >= 0) {
            #pragma unroll
            for (int u = 0; u < 4; u++) {
                float4 pv = s_p[u*1024+tid];
                g_xsel[slot*16 + 4*u+0] += s_alpha[4*u+0] * pv.x;
                g_xsel[slot*16 + 4*u+1] += s_alpha[4*u+1] * pv.y;
                g_xsel[slot*16 + 4*u+2] += s_alpha[4*u+2] * pv.z;
                g_xsel[slot*16 + 4*u+3] += s_alpha[4*u+3] * pv.w;
            }
        }
        if (it == CG_ITERS-1) break;   // final beta/barrier unused

        PUBRED(g_dotB);

        // ---- barrier C: last block computes beta/gamma/frozen ----
        BAR_ARRIVE();
        if (s_last) {
            if (tid < 16) {
                double gn = g_dotB[tid];
                float gnf = (float)gn;
                float b = g_froz[tid] ? 0.f : gnf / g_gam[tid];
                g_gam[tid] = gnf;
                if (gn <= ATOL2) g_froz[tid] = 1;
                g_ab[16 + tid] = b;
                g_dotB[tid] = 0.0;
                __threadfence();
            }
            __syncthreads();
            if (tid == 0) { g_rel2 = gen; }
            __syncthreads();
        } else {
            BAR_WAIT();
        }
        if (tid < 16) s_beta[tid] = g_ab[16 + tid];
        __syncthreads();
    }
}

// ---------------- loss ----------------
__global__ void k_loss(const float* __restrict__ infm, const float* __restrict__ start,
                       const float* __restrict__ ref, float* __restrict__ out) {
    __shared__ double sd[256];
    __shared__ double sm[256];
    int t = threadIdx.x;
    int s = t >> 4;                   // source index
    int r = t & 15;                   // receiver index
    float d = g_xsel[r*16 + s] - g_xsel[(16+r)*16 + s];
    float diff = d - ref[t];
    sd[t] = (double)diff * (double)diff;
    double lm = 0.0;
    for (int idx = t; idx < NACT; idx += 256) {
        float dd = infm[idx] - start[idx];
        lm += (double)dd * (double)dd;
    }
    sm[t] = lm;
    __syncthreads();
    for (int off = 128; off >= 1; off >>= 1) {
        if (t < off) { sd[t] += sd[t+off]; sm[t] += sm[t+off]; }
        __syncthreads();
    }
    if (t == 0) {
        float loss_data  = (float)(sd[0] / 256.0);
        float loss_model = (float)(sm[0] / (double)NACT);
        out[0] = loss_data;           // alpha = 0.0 -> total == loss_data
        out[1] = loss_data;
        out[2] = loss_model;
    }
}

// ---------------- launch ----------------
extern "C" void kernel_launch(void* const* d_in, const int* in_sizes, int n_in,
                              void* d_out, int out_size) {
    const float* infm  = (const float*)d_in[0];
    const float* start = (const float*)d_in[1];
    const float* dref  = (const float*)d_in[2];
    const int*   act   = (const int*)  d_in[3];
    const int*   sa    = (const int*)  d_in[4];
    const int*   sb    = (const int*)  d_in[5];
    const int*   rxm   = (const int*)  d_in[6];
    const int*   rxn   = (const int*)  d_in[7];
    float* out = (float*)d_out;

    static int attr_done = 0;
    if (!attr_done) {
        cudaFuncSetAttribute(k_persist, cudaFuncAttributeMaxDynamicSharedMemorySize, DSMEM);
        attr_done = 1;
    }

    k_init_sigma<<<(NCELLS+255)/256, 256>>>();
    k_scatter<<<(NACT+255)/256, 256>>>(act, infm);
    k_coeffs<<<(NCX+NCY+NCZ+255)/256, 256>>>();
    k_zero<<<(NNODES*4+255)/256, 256>>>();
    k_setb<<<1, 32>>>(sa, sb);
    k_persist<<<NBLK, NTHR, DSMEM>>>(rxm, rxn);
    k_loss<<<1, 256>>>(infm, start, dref, out);
}

// round 16
// speedup vs baseline: 1.4034x; 1.0018x over previous
#include <cuda_runtime.h>
#include <cstdint>

// ---------------- problem constants ----------------
#define NNODES 139425          // 65*65*33
#define NCELLS 131072          // 64*64*32
#define NACT   81920
#define EPSD   1.0e-7f
#define ATOL2  2.0e-12         // (1e-6)^2 * ||b||^2, ||b||^2 = 2
#define NCX 137280
#define NCY 137280
#define NCZ 135200
#define CG_ITERS 100
#define NBLK 137               // ceil(139425/1024)
#define NTHR 1024
#define DSMEM (3*4*1024*16)    // p, r, q tiles (float4): 196608 B

typedef unsigned long long u64t;
#define SGN2 0x8000000080000000ULL

// ---------------- device scratch ----------------
__device__ float4 g_r[NNODES*4];       // exchanged vector: residual r
__device__ float  g_sigma[NCELLS];
__device__ float  g_cx[NCX];
__device__ float  g_cy[NCY];
__device__ float  g_cz[NCZ];
__device__ double g_dotA[16];          // p.q accumulators
__device__ double g_dotB[16];          // r.r accumulators
__device__ float  g_xsel[32*16];
__device__ float  g_ab[32];            // alpha[0..15], beta[16..31]
__device__ float  g_gam[16];
__device__ int    g_froz[16];
__device__ unsigned g_cnt;
__device__ volatile unsigned g_rel2;

// ---------------- setup kernels ----------------
__global__ void k_init_sigma() {
    int t = blockIdx.x*blockDim.x + threadIdx.x;
    if (t < NCELLS) g_sigma[t] = 1.0e-8f;            // 1/AIR_RES
}

__global__ void k_scatter(const int* __restrict__ act, const float* __restrict__ model) {
    int t = blockIdx.x*blockDim.x + threadIdx.x;
    if (t < NACT) g_sigma[act[t]] = 1.0f / model[t];
}

__global__ void k_coeffs() {
    int t = blockIdx.x*blockDim.x + threadIdx.x;
    if (t < NCX) {
        int k = t % 33; int r = t / 33; int j = r % 65; int i = r / 65;
        float s = 0.f;
        for (int jj = j-1; jj <= j; ++jj)
            for (int kk = k-1; kk <= k; ++kk)
                if (jj >= 0 && jj < 64 && kk >= 0 && kk < 32)
                    s += g_sigma[(i*64 + jj)*32 + kk];
        g_cx[t] = 6.25f * s;                          // 0.25 * 25.0
    } else if (t < NCX + NCY) {
        int e = t - NCX;
        int k = e % 33; int r = e / 33; int j = r % 64; int i = r / 64;
        float s = 0.f;
        for (int ii = i-1; ii <= i; ++ii)
            for (int kk = k-1; kk <= k; ++kk)
                if (ii >= 0 && ii < 64 && kk >= 0 && kk < 32)
                    s += g_sigma[(ii*64 + j)*32 + kk];
        g_cy[e] = 6.25f * s;
    } else if (t < NCX + NCY + NCZ) {
        int e = t - NCX - NCY;
        int k = e % 32; int r = e / 32; int j = r % 65; int i = r / 65;
        float s = 0.f;
        for (int ii = i-1; ii <= i; ++ii)
            for (int jj = j-1; jj <= j; ++jj)
                if (ii >= 0 && ii < 64 && jj >= 0 && jj < 64)
                    s += g_sigma[(ii*64 + jj)*32 + k];
        g_cz[e] = 6.25f * s;
    }
}

// per-launch state reset (runs on every graph replay)
__global__ void k_zero() {
    int t = blockIdx.x*blockDim.x + threadIdx.x;
    if (t < NNODES*4) g_r[t] = make_float4(0.f,0.f,0.f,0.f);
    if (t < 32*16) g_xsel[t] = 0.f;
    if (t < 32) g_ab[t] = 0.f;
    if (t < 16) {
        g_gam[t] = 2.f; g_froz[t] = 0;
        g_dotA[t] = 0.0; g_dotB[t] = 0.0;
    }
    // g_cnt / g_rel2 are monotone — never reset
}

// set r = b (separate kernel: ordering vs zero-fill via launch boundary)
__global__ void k_setb(const int* __restrict__ sa, const int* __restrict__ sb) {
    int s = threadIdx.x;
    if (s < 16) {
        float* rf = (float*)g_r;
        rf[sa[s]*16 + s]  = 1.0f;
        rf[sb[s]*16 + s] -= 1.0f;
    }
}

// ---------------- packed f32x2 helpers ----------------
__device__ __forceinline__ u64t pk2(float lo, float hi) {
    u64t r; asm("mov.b64 %0, {%1,%2};" : "=l"(r) : "f"(lo), "f"(hi)); return r;
}
__device__ __forceinline__ void upk2(u64t v, float& a, float& b) {
    asm("mov.b64 {%0,%1}, %2;" : "=f"(a), "=f"(b) : "l"(v));
}
__device__ __forceinline__ u64t fma2(u64t a, u64t b, u64t c) {
    u64t r; asm("fma.rn.f32x2 %0, %1, %2, %3;" : "=l"(r) : "l"(a), "l"(b), "l"(c)); return r;
}
__device__ __forceinline__ u64t mul2(u64t a, u64t b) {
    u64t r; asm("mul.rn.f32x2 %0, %1, %2;" : "=l"(r) : "l"(a), "l"(b)); return r;
}

// folded warp reduce of 4 values across 32 lanes: 9 SHFL instead of 20.
// After fold stages, lane 8k holds total for c=(lane>>3)&3.
#define QUADRED(v0, v1, v2, v3, u)                                             \
    {                                                                          \
        float t0 = __shfl_xor_sync(0xffffffffu, (v0), 16);                     \
        float t1 = __shfl_xor_sync(0xffffffffu, (v1), 16);                     \
        float t2 = __shfl_xor_sync(0xffffffffu, (v2), 16);                     \
        float t3 = __shfl_xor_sync(0xffffffffu, (v3), 16);                     \
        float b0 = (lane & 16) ? ((v2) + t2) : ((v0) + t0);                    \
        float b1 = (lane & 16) ? ((v3) + t3) : ((v1) + t1);                    \
        t0 = __shfl_xor_sync(0xffffffffu, b0, 8);                              \
        t1 = __shfl_xor_sync(0xffffffffu, b1, 8);                              \
        float cr = (lane & 8) ? (b1 + t1) : (b0 + t0);                         \
        cr += __shfl_xor_sync(0xffffffffu, cr, 4);                             \
        cr += __shfl_xor_sync(0xffffffffu, cr, 2);                             \
        cr += __shfl_xor_sync(0xffffffffu, cr, 1);                             \
        if ((lane & 7) == 0)                                                   \
            s_red[wid*16 + 4*(u) + ((lane >> 3) & 3)] = cr;                    \
    }

// cross-warp finish + atomic publish into 16 doubles
#define PUBRED(gdst)                                                           \
    {                                                                          \
        __syncthreads();                                                       \
        if (tid < 16) {                                                        \
            float acc = 0.f;                                                   \
            _Pragma("unroll")                                                  \
            for (int w = 0; w < 32; w++) acc += s_red[w*16 + tid];             \
            atomicAdd(&(gdst)[tid], (double)acc);                              \
        }                                                                      \
    }

// barrier arrive: counter-based; sets s_last in the last-arriving block
#define BAR_ARRIVE()                                                           \
    gen++;                                                                     \
    __syncthreads();                                                           \
    if (tid == 0) {                                                            \
        __threadfence();                                                       \
        unsigned old = atomicAdd(&g_cnt, 1u);                                  \
        s_last = (old == gen*(unsigned)NBLK - 1u) ? 1 : 0;                     \
    }                                                                          \
    __syncthreads();

#define BAR_WAIT()                                                             \
    if (tid == 0) {                                                            \
        while (g_rel2 < gen) { }                                               \
        __threadfence();                                                       \
    }                                                                          \
    __syncthreads();

// packed stencil accumulate: q += c*p + (-c)*pn  for both halves
#define ACC2(pn2)                                                              \
    {                                                                          \
        qa = fma2(c2, rp.x, qa); qa = fma2(n2, (pn2).x, qa);                   \
        qb = fma2(c2, rp.y, qb); qb = fma2(n2, (pn2).y, qb);                   \
    }

// ---------------- persistent CG kernel (2 barriers / iteration) ----------------
__global__ void __launch_bounds__(NTHR, 1)
k_persist(const int* __restrict__ rxm, const int* __restrict__ rxn)
{
    extern __shared__ float4 s_dyn[];
    float4* s_p = s_dyn;               // [4][1024] p (local only)
    float4* s_r = s_dyn + 4096;        // [4][1024] r (exchanged via g_r)
    float4* s_q = s_dyn + 8192;        // [4][1024] q (local only)
    ulonglong2* s_p2 = (ulonglong2*)s_p;
    ulonglong2* s_r2 = (ulonglong2*)s_r;
    ulonglong2* s_q2 = (ulonglong2*)s_q;

    const int tid = threadIdx.x;
    const int lane = tid & 31;
    const int wid  = tid >> 5;
    const int node = blockIdx.x*NTHR + tid;
    const bool valid = node < NNODES;

    int base4 = 0;
    float cxp=0.f, cxm=0.f, cyp=0.f, cym=0.f, czp=0.f, czm=0.f;
    if (valid) {
        int k = node % 33;
        int ij = node / 33;
        int j = ij % 65;
        int i = ij / 65;
        base4 = node * 4;
        if (i < 64) cxp = g_cx[(i*65 + j)*33 + k];
        if (i > 0)  cxm = g_cx[((i-1)*65 + j)*33 + k];
        if (j < 64) cyp = g_cy[(i*64 + j)*33 + k];
        if (j > 0)  cym = g_cy[(i*64 + (j-1))*33 + k];
        if (k < 32) czp = g_cz[(i*65 + j)*32 + k];
        if (k > 0)  czm = g_cz[(i*65 + j)*32 + (k-1)];
    }

    // receiver-slot ownership (32 distinct nodes)
    int slot = -1;
    if (valid) {
        for (int r2i = 0; r2i < 16; r2i++) {
            if (node == rxm[r2i]) slot = r2i;
            if (node == rxn[r2i]) slot = 16 + r2i;
        }
    }

    // init tiles: p = 0, q = 0, r from g_r (holds b, set by k_setb)
    {
        float4 z = make_float4(0.f,0.f,0.f,0.f);
        #pragma unroll
        for (int u = 0; u < 4; u++) {
            s_p[u*1024+tid] = z;
            s_q[u*1024+tid] = z;
            s_r[u*1024+tid] = valid ? g_r[base4+u] : z;
        }
    }

    __shared__ float  s_red[32*16];
    __shared__ __align__(16) float s_alpha[16];
    __shared__ __align__(16) float s_nalpha[16];
    __shared__ __align__(16) float s_beta[16];
    __shared__ int    s_last;
    if (tid < 16) s_beta[tid] = 0.f;
    __syncthreads();

    const u64t EPS2 = pk2(EPSD, EPSD);
    unsigned gen = g_rel2;       // stable generation base from previous launch

    #pragma unroll 1
    for (int it = 0; it < CG_ITERS; ++it) {
        // ---- phase A: Ar stencil (packed); q = Ar + beta*q_old;
        //      p = r + beta*p_old; partial p.q ----
        #pragma unroll
        for (int u = 0; u < 4; u++) {
            ulonglong2 rp = s_r2[u*1024+tid];
            u64t qa = mul2(EPS2, rp.x);
            u64t qb = mul2(EPS2, rp.y);
            if (cxp != 0.f) {
                u64t c2 = pk2(cxp, cxp), n2 = c2 ^ SGN2;
                ulonglong2 pn2 = *(const ulonglong2*)&g_r[base4 + 8580 + u];
                ACC2(pn2);
            }
            if (cxm != 0.f) {
                u64t c2 = pk2(cxm, cxm), n2 = c2 ^ SGN2;
                ulonglong2 pn2 = *(const ulonglong2*)&g_r[base4 - 8580 + u];
                ACC2(pn2);
            }
            if (cyp != 0.f) {
                u64t c2 = pk2(cyp, cyp), n2 = c2 ^ SGN2;
                ulonglong2 pn2 = (tid + 33 < NTHR) ? s_r2[u*1024+tid+33]
                                 : *(const ulonglong2*)&g_r[base4 + 132 + u];
                ACC2(pn2);
            }
            if (cym != 0.f) {
                u64t c2 = pk2(cym, cym), n2 = c2 ^ SGN2;
                ulonglong2 pn2 = (tid >= 33) ? s_r2[u*1024+tid-33]
                                 : *(const ulonglong2*)&g_r[base4 - 132 + u];
                ACC2(pn2);
            }
            if (czp != 0.f) {
                u64t c2 = pk2(czp, czp), n2 = c2 ^ SGN2;
                ulonglong2 pn2 = (tid + 1 < NTHR) ? s_r2[u*1024+tid+1]
                                 : *(const ulonglong2*)&g_r[base4 + 4 + u];
                ACC2(pn2);
            }
            if (czm != 0.f) {
                u64t c2 = pk2(czm, czm), n2 = c2 ^ SGN2;
                ulonglong2 pn2 = (tid >= 1) ? s_r2[u*1024+tid-1]
                                 : *(const ulonglong2*)&g_r[base4 - 4 + u];
                ACC2(pn2);
            }
            // q = Ar + beta*q_old ; p = r + beta*p_old  (packed beta pairs)
            const u64t* bp = (const u64t*)s_beta;
            u64t b01 = bp[2*u], b23 = bp[2*u+1];
            ulonglong2 qo = s_q2[u*1024+tid];
            ulonglong2 po = s_p2[u*1024+tid];
            qa = fma2(b01, qo.x, qa);
            qb = fma2(b23, qo.y, qb);
            u64t na = fma2(b01, po.x, rp.x);
            u64t nb = fma2(b23, po.y, rp.y);
            s_q2[u*1024+tid] = make_ulonglong2(qa, qb);
            s_p2[u*1024+tid] = make_ulonglong2(na, nb);
            u64t pr1 = mul2(na, qa), pr2 = mul2(nb, qb);
            float f0, f1, f2, f3;
            upk2(pr1, f0, f1); upk2(pr2, f2, f3);
            QUADRED(f0, f1, f2, f3, u);
        }
        PUBRED(g_dotA);

        // ---- barrier B: last block computes alpha from g_dotA ----
        BAR_ARRIVE();
        if (s_last) {
            if (tid < 16) {
                double pq = g_dotA[tid];
                float a = g_froz[tid] ? 0.f : g_gam[tid] / (float)pq;
                g_ab[tid] = a;
                g_dotA[tid] = 0.0;
                __threadfence();
            }
            __syncthreads();
            if (tid == 0) { g_rel2 = gen; }
            __syncthreads();
        } else {
            BAR_WAIT();
        }
        if (tid < 16) {
            float a = g_ab[tid];
            s_alpha[tid] = a;
            s_nalpha[tid] = -a;
        }
        __syncthreads();

        // ---- phase B: r -= alpha q (packed, smem + publish);
        //      x_rx += alpha p; r.r ----
        #pragma unroll
        for (int u = 0; u < 4; u++) {
            const u64t* nap = (const u64t*)s_nalpha;
            u64t na01 = nap[2*u], na23 = nap[2*u+1];
            ulonglong2 rp = s_r2[u*1024+tid];
            ulonglong2 qp = s_q2[u*1024+tid];
            u64t ra = fma2(na01, qp.x, rp.x);
            u64t rb = fma2(na23, qp.y, rp.y);
            ulonglong2 rn = make_ulonglong2(ra, rb);
            s_r2[u*1024+tid] = rn;
            if (valid) *(ulonglong2*)&g_r[base4+u] = rn;
            u64t rr1 = mul2(ra, ra), rr2 = mul2(rb, rb);
            float f0, f1, f2, f3;
            upk2(rr1, f0, f1); upk2(rr2, f2, f3);
            QUADRED(f0, f1, f2, f3, u);
        }
        if (slot >= 0) {
            #pragma unroll
            for (int u = 0; u < 4; u++) {
                float4 pv = s_p[u*1024+tid];
                g_xsel[slot*16 + 4*u+0] += s_alpha[4*u+0] * pv.x;
                g_xsel[slot*16 + 4*u+1] += s_alpha[4*u+1] * pv.y;
                g_xsel[slot*16 + 4*u+2] += s_alpha[4*u+2] * pv.z;
                g_xsel[slot*16 + 4*u+3] += s_alpha[4*u+3] * pv.w;
            }
        }
        if (it == CG_ITERS-1) break;   // final beta/barrier unused

        PUBRED(g_dotB);

        // ---- barrier C: last block computes beta/gamma/frozen ----
        BAR_ARRIVE();
        if (s_last) {
            if (tid < 16) {
                double gn = g_dotB[tid];
                float gnf = (float)gn;
                float b = g_froz[tid] ? 0.f : gnf / g_gam[tid];
                g_gam[tid] = gnf;
                if (gn <= ATOL2) g_froz[tid] = 1;
                g_ab[16 + tid] = b;
                g_dotB[tid] = 0.0;
                __threadfence();
            }
            __syncthreads();
            if (tid == 0) { g_rel2 = gen; }
            __syncthreads();
        } else {
            BAR_WAIT();
        }
        if (tid < 16) s_beta[tid] = g_ab[16 + tid];
        __syncthreads();
    }
}

// ---------------- loss ----------------
__global__ void k_loss(const float* __restrict__ infm, const float* __restrict__ start,
                       const float* __restrict__ ref, float* __restrict__ out) {
    __shared__ double sd[256];
    __shared__ double sm[256];
    int t = threadIdx.x;
    int s = t >> 4;                   // source index
    int r = t & 15;                   // receiver index
    float d = g_xsel[r*16 + s] - g_xsel[(16+r)*16 + s];
    float diff = d - ref[t];
    sd[t] = (double)diff * (double)diff;
    double lm = 0.0;
    for (int idx = t; idx < NACT; idx += 256) {
        float dd = infm[idx] - start[idx];
        lm += (double)dd * (double)dd;
    }
    sm[t] = lm;
    __syncthreads();
    for (int off = 128; off >= 1; off >>= 1) {
        if (t < off) { sd[t] += sd[t+off]; sm[t] += sm[t+off]; }
        __syncthreads();
    }
    if (t == 0) {
        float loss_data  = (float)(sd[0] / 256.0);
        float loss_model = (float)(sm[0] / (double)NACT);
        out[0] = loss_data;           // alpha = 0.0 -> total == loss_data
        out[1] = loss_data;
        out[2] = loss_model;
    }
}

// ---------------- launch ----------------
extern "C" void kernel_launch(void* const* d_in, const int* in_sizes, int n_in,
                              void* d_out, int out_size) {
    const float* infm  = (const float*)d_in[0];
    const float* start = (const float*)d_in[1];
    const float* dref  = (const float*)d_in[2];
    const int*   act   = (const int*)  d_in[3];
    const int*   sa    = (const int*)  d_in[4];
    const int*   sb    = (const int*)  d_in[5];
    const int*   rxm   = (const int*)  d_in[6];
    const int*   rxn   = (const int*)  d_in[7];
    float* out = (float*)d_out;

    static int attr_done = 0;
    if (!attr_done) {
        cudaFuncSetAttribute(k_persist, cudaFuncAttributeMaxDynamicSharedMemorySize, DSMEM);
        attr_done = 1;
    }

    k_init_sigma<<<(NCELLS+255)/256, 256>>>();
    k_scatter<<<(NACT+255)/256, 256>>>(act, infm);
    k_coeffs<<<(NCX+NCY+NCZ+255)/256, 256>>>();
    k_zero<<<(NNODES*4+255)/256, 256>>>();
    k_setb<<<1, 32>>>(sa, sb);
    k_persist<<<NBLK, NTHR, DSMEM>>>(rxm, rxn);
    k_loss<<<1, 256>>>(infm, start, dref, out);
}